// round 15
// baseline (speedup 1.0000x reference)
#include <cuda_runtime.h>
#include <cuda_fp16.h>
#include <cstdint>

// ============================================================================
// IndRNN on GB300 — batch-paired single kernel, zero device scratch:
//   128 CTAs x 512 threads (occ 1, one uniform wave). Warps 0-7 = batch 2*by,
//   warps 8-15 = batch 2*by+1; groups fully independent after the prologue,
//   each synced by its own named barrier. Shared resident B (W^T fp16, ROWB=80
//   padded, built once via coalesced smem-staged transpose). Per group:
//   R7/R8-proven mainloop (LDG fp32 A -> cvt fp16 -> STS, 2-stage ring,
//   1 barrier/chunk, 32x64 warp tiles) + half-tile dump+scan epilogue.
// Shapes: B=64, T=512, D(K)=256, U(N)=512, M=B*T=32768
// rel_err ~ 2.35e-4 (bit-identical roundings/accumulation to R5-R14).
// ============================================================================

#define U_DIM 512
#define K_DIM 256
#define T_DIM 512
#define MT 128
#define NT 128
#define KC 32
#define ROWB 80                      // padded row stride, conflict-free ldmatrix
#define SUBT (128 * ROWB)            // 128x32 fp16 subtile: 10240 B
#define B_BASE 0                     // resident B: 8 subtiles = 81920 B
#define A_BASE 81920                 // A rings: 2 groups x 2 stages = 40960 B
#define SC_BASE (81920 + 40960)      // scan buffers: 2 x 33280 B
#define SCROW 130
#define SCB_G 33280                  // 64 * 130 * 4
#define SMEM_BYTES (SC_BASE + 2 * SCB_G)   // 189440 B -> occ 1

// ---------------------------------------------------------------- helpers
__device__ __forceinline__ uint32_t smem_u32(const void* p) {
    uint32_t a;
    asm("{ .reg .u64 t; cvta.to.shared.u64 t, %1; cvt.u32.u64 %0, t; }"
        : "=r"(a) : "l"(p));
    return a;
}
__device__ __forceinline__ void ldsm_x4(uint32_t* r, uint32_t addr) {
    asm volatile("ldmatrix.sync.aligned.m8n8.x4.shared.b16 {%0,%1,%2,%3}, [%4];"
                 : "=r"(r[0]), "=r"(r[1]), "=r"(r[2]), "=r"(r[3]) : "r"(addr));
}
__device__ __forceinline__ void mma_f16(float* c, const uint32_t* a,
                                        uint32_t b0, uint32_t b1) {
    asm volatile(
        "mma.sync.aligned.m16n8k16.row.col.f32.f16.f16.f32 "
        "{%0,%1,%2,%3}, {%4,%5,%6,%7}, {%8,%9}, {%0,%1,%2,%3};"
        : "+f"(c[0]), "+f"(c[1]), "+f"(c[2]), "+f"(c[3])
        : "r"(a[0]), "r"(a[1]), "r"(a[2]), "r"(a[3]), "r"(b0), "r"(b1));
}
#define NB_SYNC(id) asm volatile("bar.sync %0, 256;" :: "r"(id) : "memory")

__device__ __forceinline__ uint32_t pack_h2(__half a, __half b) {
    __half2 p(a, b);
    return *reinterpret_cast<uint32_t*>(&p);
}
__device__ __forceinline__ void sts8(uint32_t dst, uint32_t v0, uint32_t v1) {
    asm volatile("st.shared.v2.b32 [%0], {%1, %2};"
                 :: "r"(dst), "r"(v0), "r"(v1) : "memory");
}

// ---------------------------------------------------------------- kernel
__global__ __launch_bounds__(512, 1)
void indrnn_pair_kernel(const float* __restrict__ W,     // [K, N] fp32
                        const float* __restrict__ X,     // [M, K] fp32
                        const float* __restrict__ bias,  // [N]
                        const float* __restrict__ h0g,   // [B, U]
                        const float* __restrict__ ug,    // [U]
                        float* __restrict__ C)           // [M, U_DIM]
{
    extern __shared__ char smem[];
    const uint32_t sb = smem_u32(smem);

    const int tid  = threadIdx.x;
    const int lane = tid & 31;
    const int wid  = tid >> 5;
    const int g    = wid >> 3;            // group 0/1 (batch within pair)
    const int wl   = wid & 7;             // warp-in-group
    const int wm   = wl & 3;
    const int wn   = wl >> 2;
    const int tg   = tid & 255;           // thread-in-group
    const int n0   = blockIdx.x * NT;
    const int b    = blockIdx.y * 2 + g;
    const int mB   = b * T_DIM;
    const int barid = 1 + g;

    // ============ prologue (all 512 threads): resident B = W^T fp16 ============
    {
        float* stg = reinterpret_cast<float*>(smem + SC_BASE);  // staging, free now
        #pragma unroll 1
        for (int kb = 0; kb < 4; kb++) {
            const int k0 = kb * 64;
            // coalesced load 64k x 128n, transposed store into staging (stride 67)
            #pragma unroll
            for (int i = 0; i < 16; i++) {
                int idx = i * 512 + tid;
                int r = idx >> 7, c = idx & 127;
                stg[c * 67 + r] = W[(size_t)(k0 + r) * U_DIM + n0 + c];
            }
            __syncthreads();
            // write B rows: thread owns n = tid>>2, k quarter kq = tid&3
            const int n  = tid >> 2;
            const int kq = tid & 3;
            const int sc = 2 * kb + (kq >> 1);
            const int koff = (kq & 1) * 16;
            const uint32_t dst = sb + (uint32_t)(B_BASE + sc * SUBT + n * ROWB + koff * 2);
            float v[16];
            #pragma unroll
            for (int j = 0; j < 16; j++)
                v[j] = stg[n * 67 + kq * 16 + j];
            #pragma unroll
            for (int q = 0; q < 4; q++)
                sts8(dst + q * 8,
                     pack_h2(__float2half_rn(v[q*4+0]), __float2half_rn(v[q*4+1])),
                     pack_h2(__float2half_rn(v[q*4+2]), __float2half_rn(v[q*4+3])));
            __syncthreads();
        }
    }
    // groups fully independent from here on (named barriers only)

    float* const scf = reinterpret_cast<float*>(smem + SC_BASE + g * SCB_G);
    const uint32_t aRing = (uint32_t)(A_BASE + g * 2 * SUBT);

    // scan state: thread tg<128 owns column n0+tg
    float h = 0.0f, uc = 0.0f;
    if (tg < 128) {
        uc = fminf(fmaxf(ug[n0 + tg], 0.0f), 1.0f);
        h  = h0g[(size_t)b * U_DIM + n0 + tg];
    }

    // A load mapping: 4 float4/thread (128 rows x 8 float4 cols)
    const int aRow[4] = { (0*256 + tg) >> 3, (1*256 + tg) >> 3,
                          (2*256 + tg) >> 3, (3*256 + tg) >> 3 };
    const int aC4 = tg & 7;
    // ldmatrix lane offsets (R8-proven, ROWB-padded)
    const uint32_t aOff = (uint32_t)((lane & 15) * ROWB + (lane >> 4) * 16);
    const uint32_t bOff = (uint32_t)(((lane & 7) + ((lane >> 4) & 1) * 8) * ROWB
                                     + ((lane >> 3) & 1) * 16);
    // dump fragment coords
    const int colBase = wn * 64 + (lane & 3) * 2;
    const int rowBase = wm * 32 + (lane >> 2);

    float4 rA[4];
    auto ldg_chunk = [&](int ch) {
        const size_t mrow = (size_t)(mB + ((ch >> 3) << 7));
        const int kk = (ch & 7) * KC;
        #pragma unroll
        for (int i = 0; i < 4; i++)
            rA[i] = *reinterpret_cast<const float4*>(
                X + (mrow + aRow[i]) * K_DIM + kk + aC4 * 4);
    };
    auto sts_chunk = [&](int ch) {
        const uint32_t st = sb + aRing + (uint32_t)((ch & 1) * SUBT);
        #pragma unroll
        for (int i = 0; i < 4; i++) {
            __half hx = __float2half_rn(rA[i].x), hy = __float2half_rn(rA[i].y);
            __half hz = __float2half_rn(rA[i].z), hw = __float2half_rn(rA[i].w);
            sts8(st + (uint32_t)(aRow[i] * ROWB + aC4 * 8),
                 pack_h2(hx, hy), pack_h2(hz, hw));
        }
    };

    ldg_chunk(0);
    sts_chunk(0);

    #pragma unroll 1
    for (int tc = 0; tc < 4; tc++) {
        const int m0 = mB + tc * MT;

        float acc[2][8][4];
        #pragma unroll
        for (int mt = 0; mt < 2; mt++)
            #pragma unroll
            for (int nt = 0; nt < 8; nt++)
                #pragma unroll
                for (int q = 0; q < 4; q++)
                    acc[mt][nt][q] = 0.0f;

        #pragma unroll 1
        for (int c = 0; c < 8; c++) {
            const int ch = tc * 8 + c;
            if (ch + 1 < 32) ldg_chunk(ch + 1);    // overlap global latency
            NB_SYNC(barid);                        // publish stage ch&1

            const uint32_t uA = sb + aRing + (uint32_t)((ch & 1) * SUBT);
            const uint32_t uB = sb + (uint32_t)(B_BASE + (ch & 7) * SUBT);
            #pragma unroll
            for (int ks = 0; ks < 2; ks++) {
                const uint32_t kb = ks * 32;
                uint32_t ah[2][4];
                #pragma unroll
                for (int mt = 0; mt < 2; mt++)
                    ldsm_x4(ah[mt], uA + (uint32_t)((wm * 32 + mt * 16) * ROWB) + aOff + kb);
                #pragma unroll
                for (int np = 0; np < 4; np++) {
                    uint32_t bh[4];
                    ldsm_x4(bh, uB + (uint32_t)((wn * 64 + np * 16) * ROWB) + bOff + kb);
                    #pragma unroll
                    for (int mt = 0; mt < 2; mt++) {
                        mma_f16(acc[mt][np * 2 + 0], ah[mt], bh[0], bh[1]);
                        mma_f16(acc[mt][np * 2 + 1], ah[mt], bh[2], bh[3]);
                    }
                }
            }
            if (ch + 1 < 32) sts_chunk(ch + 1);    // other stage; safe post-bar
        }

        // ---- two half-tile dump+scan phases (rows p*64 .. p*64+63) ----
        #pragma unroll 1
        for (int p = 0; p < 2; p++) {
            NB_SYNC(barid);    // prev phase's scan reads done / mainloop done
            if ((wm >> 1) == p) {
                const int rloc = rowBase - p * 64;   // 0..63 for owning warps
                #pragma unroll
                for (int nt = 0; nt < 8; nt++) {
                    const int col = colBase + nt * 8;
                    float2 bv = *reinterpret_cast<const float2*>(bias + n0 + col);
                    #pragma unroll
                    for (int mt = 0; mt < 2; mt++) {
                        const int r = rloc + mt * 16;
                        float2 o0 = { acc[mt][nt][0] + bv.x, acc[mt][nt][1] + bv.y };
                        float2 o1 = { acc[mt][nt][2] + bv.x, acc[mt][nt][3] + bv.y };
                        *reinterpret_cast<float2*>(scf + (size_t)r * SCROW + col)       = o0;
                        *reinterpret_cast<float2*>(scf + (size_t)(r + 8) * SCROW + col) = o1;
                    }
                }
            }
            NB_SYNC(barid);
            if (tg < 128) {
                float* crow = C + (size_t)(m0 + p * 64) * U_DIM + n0 + tg;
                #pragma unroll
                for (int t = 0; t < 64; t += 8) {
                    float v[8];
                    #pragma unroll
                    for (int i = 0; i < 8; i++)
                        v[i] = scf[(size_t)(t + i) * SCROW + tg];
                    #pragma unroll
                    for (int i = 0; i < 8; i++) {
                        h = fmaxf(fmaf(h, uc, v[i]), 0.0f);
                        v[i] = h;
                    }
                    #pragma unroll
                    for (int i = 0; i < 8; i++)
                        crow[(size_t)(t + i) * U_DIM] = v[i];
                }
            }
        }
        NB_SYNC(barid);    // scan reads done before next tile's dump
    }
}

// ---------------------------------------------------------------- launch
extern "C" void kernel_launch(void* const* d_in, const int* in_sizes, int n_in,
                              void* d_out, int out_size)
{
    const float* x  = (const float*)d_in[0];  // [B,T,D]
    const float* h0 = (const float*)d_in[1];  // [B,U]
    const float* W  = (const float*)d_in[2];  // [D,U]
    const float* u  = (const float*)d_in[3];  // [U]
    const float* bb = (const float*)d_in[4];  // [U]
    float* out = (float*)d_out;               // [B,T,U]

    const int U = in_sizes[3];                // 512
    const int B = in_sizes[1] / U;            // 64

    cudaFuncSetAttribute(indrnn_pair_kernel,
                         cudaFuncAttributeMaxDynamicSharedMemorySize, SMEM_BYTES);
    dim3 gg(U / NT, B / 2);   // (4, 32) = 128 CTAs, occ 1, one uniform wave
    indrnn_pair_kernel<<<gg, 512, SMEM_BYTES>>>(W, x, bb, h0, u, out);
}